// round 13
// baseline (speedup 1.0000x reference)
#include <cuda_runtime.h>
#include <cstdint>

#define N_NODES 50000
#define N_EDGES 1600000
#define IN_DIM  256
#define HID     128
#define NCLS    40
#define NEG     0.2f
#define FULL    0xffffffffu

// ---------------- scratch (device globals: allocation-free) ----------------
__device__ __align__(16) float g_h0[(size_t)N_NODES * HID];   // layer0 transformed feats
__device__ __align__(16) float g_hr[(size_t)N_NODES * HID];   // relu(layer0 out)
__device__ __align__(16) float g_h1[(size_t)N_NODES * NCLS];
__device__ float g_as0[N_NODES], g_ad0[N_NODES];
__device__ float g_as1[N_NODES], g_ad1[N_NODES];
__device__ int   g_src[N_EDGES], g_dst[N_EDGES];
__device__ int   g_col[N_EDGES];                  // CSR: src ids grouped by dst
__device__ int   g_deg[N_NODES];
__device__ int   g_rowptr[N_NODES + 1];
__device__ int   g_cur[N_NODES];

__device__ __forceinline__ float lrelu(float v) { return v > 0.f ? v : NEG * v; }
__device__ __forceinline__ int clampN(int v) {
    v = v < 0 ? 0 : v;
    return v >= N_NODES ? N_NODES - 1 : v;
}

// ---------------- zero degree histogram ----------------
__global__ void k_zero() {
    int i = blockIdx.x * blockDim.x + threadIdx.x;
    if (i < N_NODES) g_deg[i] = 0;
}

// ------- edge index load (dtype-robust) + degree histogram fused -------
// JAX default config disables x64, so the "int64" edge_index is usually int32.
// If genuine little-endian int64, all high words are zero (ids < 50000).
__global__ void k_convert(const int* __restrict__ ei32) {
    int i = blockIdx.x * blockDim.x + threadIdx.x;
    if (i >= N_EDGES) return;
    bool is64 = (ei32[1] == 0) & (ei32[3] == 0) & (ei32[5] == 0) & (ei32[7] == 0)
              & (ei32[9] == 0) & (ei32[11] == 0) & (ei32[13] == 0) & (ei32[15] == 0);
    int s, t;
    if (is64) {
        const long long* e = reinterpret_cast<const long long*>(ei32);
        s = (int)e[i];
        t = (int)e[i + N_EDGES];
    } else {
        s = ei32[i];
        t = ei32[i + N_EDGES];
    }
    s = clampN(s); t = clampN(t);
    g_src[i] = s;
    g_dst[i] = t;
    atomicAdd(&g_deg[t], 1);
}

// ---------------- single-block exclusive scan of degrees ----------------
__global__ void k_scan() {
    __shared__ int warp_sums[32];
    __shared__ int s_run;
    int tid  = threadIdx.x;          // 1024 threads
    int lane = tid & 31, wid = tid >> 5;
    if (tid == 0) s_run = 0;
    __syncthreads();
    for (int base = 0; base < N_NODES; base += 1024) {
        int i = base + tid;
        int v = (i < N_NODES) ? g_deg[i] : 0;
        int x = v;
        #pragma unroll
        for (int o = 1; o < 32; o <<= 1) {
            int t = __shfl_up_sync(FULL, x, o);
            if (lane >= o) x += t;
        }
        if (lane == 31) warp_sums[wid] = x;
        __syncthreads();
        if (wid == 0) {
            int w = warp_sums[lane];
            int y = w;
            #pragma unroll
            for (int o = 1; o < 32; o <<= 1) {
                int t = __shfl_up_sync(FULL, y, o);
                if (lane >= o) y += t;
            }
            warp_sums[lane] = y - w;          // exclusive warp offsets
        }
        __syncthreads();
        int excl = s_run + warp_sums[wid] + x - v;
        if (i < N_NODES) { g_rowptr[i] = excl; g_cur[i] = excl; }
        __syncthreads();                       // all reads of s_run done
        if (tid == 1023) s_run += warp_sums[31] + x;
        __syncthreads();
    }
    if (tid == 0) g_rowptr[N_NODES] = s_run;
}

// ---------------- scatter edges into CSR buckets ----------------
__global__ void k_scatter() {
    int i = blockIdx.x * blockDim.x + threadIdx.x;   // exact grid
    int t = g_dst[i];
    int pos = atomicAdd(&g_cur[t], 1);
    g_col[pos] = g_src[i];
}

// ---------------- layer0 GEMM: h0 = x[50000,256] @ W0[128,256]^T ------------
__global__ __launch_bounds__(256) void k_gemm0(const float* __restrict__ A,
                                               const float* __restrict__ B) {
    __shared__ float As[16][132];
    __shared__ float Bs[16][132];
    int tid = threadIdx.x;
    int m0  = blockIdx.x * 128;
    int tx  = tid & 15;
    int ty  = tid >> 4;
    float acc[8][8] = {};

    for (int k0 = 0; k0 < IN_DIM; k0 += 16) {
        #pragma unroll
        for (int i = 0; i < 2; i++) {
            int li  = tid + i * 256;
            int row = li >> 2, f4 = li & 3;
            int gr  = m0 + row;
            float4 v = (gr < N_NODES)
                ? *reinterpret_cast<const float4*>(A + (size_t)gr * IN_DIM + k0 + f4 * 4)
                : make_float4(0.f, 0.f, 0.f, 0.f);
            As[f4*4+0][row] = v.x; As[f4*4+1][row] = v.y;
            As[f4*4+2][row] = v.z; As[f4*4+3][row] = v.w;

            float4 w = *reinterpret_cast<const float4*>(B + (size_t)row * IN_DIM + k0 + f4 * 4);
            Bs[f4*4+0][row] = w.x; Bs[f4*4+1][row] = w.y;
            Bs[f4*4+2][row] = w.z; Bs[f4*4+3][row] = w.w;
        }
        __syncthreads();
        #pragma unroll
        for (int k = 0; k < 16; k++) {
            float a[8], b[8];
            #pragma unroll
            for (int i = 0; i < 8; i++) a[i] = As[k][ty * 8 + i];
            #pragma unroll
            for (int j = 0; j < 8; j++) b[j] = Bs[k][tx * 8 + j];
            #pragma unroll
            for (int i = 0; i < 8; i++)
                #pragma unroll
                for (int j = 0; j < 8; j++) acc[i][j] += a[i] * b[j];
        }
        __syncthreads();
    }
    #pragma unroll
    for (int i = 0; i < 8; i++) {
        int r = m0 + ty * 8 + i;
        if (r < N_NODES) {
            float* cp = g_h0 + (size_t)r * HID + tx * 8;
            *reinterpret_cast<float4*>(cp)     = make_float4(acc[i][0], acc[i][1], acc[i][2], acc[i][3]);
            *reinterpret_cast<float4*>(cp + 4) = make_float4(acc[i][4], acc[i][5], acc[i][6], acc[i][7]);
        }
    }
}

// ---------------- layer0 node init: alpha dot products only ----------------
__global__ __launch_bounds__(256) void k_nodeinit0(const float* __restrict__ av,
                                                   const float* __restrict__ dv) {
    int n    = blockIdx.x * 8 + (threadIdx.x >> 5);
    int lane = threadIdx.x & 31;
    float4 h  = *reinterpret_cast<const float4*>(g_h0 + (size_t)n * HID + lane * 4);
    float4 a4 = *reinterpret_cast<const float4*>(av + lane * 4);
    float4 d4 = *reinterpret_cast<const float4*>(dv + lane * 4);
    float s = h.x*a4.x + h.y*a4.y + h.z*a4.z + h.w*a4.w;
    float d = h.x*d4.x + h.y*d4.y + h.z*d4.z + h.w*d4.w;
    #pragma unroll
    for (int o = 16; o; o >>= 1) {
        s += __shfl_xor_sync(FULL, s, o);
        d += __shfl_xor_sync(FULL, d, o);
    }
    if (lane == 0) { g_as0[n] = s; g_ad0[n] = d; }
}

// ------- layer0 pull aggregation + softmax + finalize (fused), warp/node -------
__global__ __launch_bounds__(256) void k_pull0(const float* __restrict__ b0) {
    int n    = blockIdx.x * 8 + (threadIdx.x >> 5);      // exact: 6250*8 = 50000
    int lane = threadIdx.x & 31;
    const float* hp = g_h0 + (size_t)n * HID + lane * 4;
    float4 hs  = *reinterpret_cast<const float4*>(hp);
    float adn  = g_ad0[n];
    float exs  = __expf(lrelu(g_as0[n] + adn));          // self-loop (no max-shift; safe range)
    float4 acc = make_float4(hs.x*exs, hs.y*exs, hs.z*exs, hs.w*exs);
    float den  = (lane == 0) ? exs : 0.f;

    int beg = g_rowptr[n], end = g_rowptr[n + 1];
    for (int base = beg; base < end; base += 32) {
        int e = base + lane;
        int s = 0; float ex = 0.f;
        if (e < end) {
            s  = g_col[e];
            ex = __expf(lrelu(g_as0[s] + adn));
            den += ex;
        }
        int cnt = end - base; if (cnt > 32) cnt = 32;
        if (cnt == 32) {
            #pragma unroll 8
            for (int j = 0; j < 32; j++) {
                float exj = __shfl_sync(FULL, ex, j);
                int   sj  = __shfl_sync(FULL, s, j);
                float4 h = *reinterpret_cast<const float4*>(g_h0 + (size_t)sj * HID + lane * 4);
                acc.x += h.x*exj; acc.y += h.y*exj; acc.z += h.z*exj; acc.w += h.w*exj;
            }
        } else {
            for (int j = 0; j < cnt; j++) {
                float exj = __shfl_sync(FULL, ex, j);
                int   sj  = __shfl_sync(FULL, s, j);
                float4 h = *reinterpret_cast<const float4*>(g_h0 + (size_t)sj * HID + lane * 4);
                acc.x += h.x*exj; acc.y += h.y*exj; acc.z += h.z*exj; acc.w += h.w*exj;
            }
        }
    }
    #pragma unroll
    for (int o = 16; o; o >>= 1) den += __shfl_xor_sync(FULL, den, o);
    float inv = __fdividef(1.f, den);
    float4 b = *reinterpret_cast<const float4*>(b0 + lane * 4);
    float4 r;
    r.x = fmaxf(acc.x*inv + b.x, 0.f);
    r.y = fmaxf(acc.y*inv + b.y, 0.f);
    r.z = fmaxf(acc.z*inv + b.z, 0.f);
    r.w = fmaxf(acc.w*inv + b.w, 0.f);
    *reinterpret_cast<float4*>(g_hr + (size_t)n * HID + lane * 4) = r;
}

// ---------------- layer1 GEMM: h1 = hr[50000,128] @ W1[40,128]^T -------------
__global__ __launch_bounds__(256) void k_gemm1(const float* __restrict__ B) {
    __shared__ float hs[32][132];
    __shared__ float ws[32][42];
    int tid = threadIdx.x;
    int m0  = blockIdx.x * 128;
    int tx  = tid & 7;
    int ty  = tid >> 3;
    float acc[4][5] = {};

    for (int k0 = 0; k0 < HID; k0 += 32) {
        #pragma unroll
        for (int i = 0; i < 4; i++) {
            int li  = tid + i * 256;
            int row = li >> 3, f4 = li & 7;
            int gr  = m0 + row;
            float4 v = (gr < N_NODES)
                ? *reinterpret_cast<const float4*>(g_hr + (size_t)gr * HID + k0 + f4 * 4)
                : make_float4(0.f, 0.f, 0.f, 0.f);
            hs[f4*4+0][row] = v.x; hs[f4*4+1][row] = v.y;
            hs[f4*4+2][row] = v.z; hs[f4*4+3][row] = v.w;
        }
        for (int idx = tid; idx < 40 * 32; idx += 256) {
            int j = idx >> 5, k = idx & 31;
            ws[k][j] = B[(size_t)j * HID + k0 + k];
        }
        __syncthreads();
        #pragma unroll
        for (int k = 0; k < 32; k++) {
            float a[4], b[5];
            #pragma unroll
            for (int i = 0; i < 4; i++) a[i] = hs[k][ty * 4 + i];
            #pragma unroll
            for (int j = 0; j < 5; j++) b[j] = ws[k][tx * 5 + j];
            #pragma unroll
            for (int i = 0; i < 4; i++)
                #pragma unroll
                for (int j = 0; j < 5; j++) acc[i][j] += a[i] * b[j];
        }
        __syncthreads();
    }
    #pragma unroll
    for (int i = 0; i < 4; i++) {
        int r = m0 + ty * 4 + i;
        if (r < N_NODES)
            #pragma unroll
            for (int j = 0; j < 5; j++)
                g_h1[(size_t)r * NCLS + tx * 5 + j] = acc[i][j];
    }
}

// ---------------- layer1 node init: alpha dots only ----------------
__global__ __launch_bounds__(256) void k_nodeinit1(const float* __restrict__ av,
                                                   const float* __restrict__ dv) {
    int n    = blockIdx.x * 8 + (threadIdx.x >> 5);
    int lane = threadIdx.x & 31;
    const float* hp = g_h1 + (size_t)n * NCLS;
    float ha = hp[lane];
    float hb = (lane < 8) ? hp[32 + lane] : 0.f;
    float s = ha * av[lane] + ((lane < 8) ? hb * av[32 + lane] : 0.f);
    float d = ha * dv[lane] + ((lane < 8) ? hb * dv[32 + lane] : 0.f);
    #pragma unroll
    for (int o = 16; o; o >>= 1) {
        s += __shfl_xor_sync(FULL, s, o);
        d += __shfl_xor_sync(FULL, d, o);
    }
    if (lane == 0) { g_as1[n] = s; g_ad1[n] = d; }
}

// ------- layer1 pull aggregation + finalize (fused), warp/node -------
__global__ __launch_bounds__(256) void k_pull1(const float* __restrict__ b1,
                                               float* __restrict__ out) {
    int n    = blockIdx.x * 8 + (threadIdx.x >> 5);
    int lane = threadIdx.x & 31;
    float adn = g_ad1[n];
    float exs = __expf(lrelu(g_as1[n] + adn));
    float4 acc = make_float4(0.f, 0.f, 0.f, 0.f);
    if (lane < 10) {
        float4 h = *reinterpret_cast<const float4*>(g_h1 + (size_t)n * NCLS + lane * 4);
        acc = make_float4(h.x*exs, h.y*exs, h.z*exs, h.w*exs);
    }
    float den = (lane == 0) ? exs : 0.f;

    int beg = g_rowptr[n], end = g_rowptr[n + 1];
    for (int base = beg; base < end; base += 32) {
        int e = base + lane;
        int s = 0; float ex = 0.f;
        if (e < end) {
            s  = g_col[e];
            ex = __expf(lrelu(g_as1[s] + adn));
            den += ex;
        }
        int cnt = end - base; if (cnt > 32) cnt = 32;
        #pragma unroll 8
        for (int j = 0; j < cnt; j++) {
            float exj = __shfl_sync(FULL, ex, j);
            int   sj  = __shfl_sync(FULL, s, j);
            if (lane < 10) {
                float4 h = *reinterpret_cast<const float4*>(g_h1 + (size_t)sj * NCLS + lane * 4);
                acc.x += h.x*exj; acc.y += h.y*exj; acc.z += h.z*exj; acc.w += h.w*exj;
            }
        }
    }
    #pragma unroll
    for (int o = 16; o; o >>= 1) den += __shfl_xor_sync(FULL, den, o);
    float inv = __fdividef(1.f, den);
    if (lane < 10) {
        const float* bp = b1 + lane * 4;
        float* op = out + (size_t)n * NCLS + lane * 4;
        op[0] = acc.x*inv + bp[0];
        op[1] = acc.y*inv + bp[1];
        op[2] = acc.z*inv + bp[2];
        op[3] = acc.w*inv + bp[3];
    }
}

// ---------------- launch ----------------
extern "C" void kernel_launch(void* const* d_in, const int* in_sizes, int n_in,
                              void* d_out, int out_size) {
    const float* x      = (const float*)d_in[0];
    const int*   ei     = (const int*)d_in[1];       // int32 or int64 — sniffed on device
    const float* W0     = (const float*)d_in[2];
    const float* a_src0 = (const float*)d_in[3];
    const float* a_dst0 = (const float*)d_in[4];
    const float* b0     = (const float*)d_in[5];
    const float* W1     = (const float*)d_in[6];
    const float* a_src1 = (const float*)d_in[7];
    const float* a_dst1 = (const float*)d_in[8];
    const float* b1     = (const float*)d_in[9];
    float*       out    = (float*)d_out;

    k_zero     <<<(N_NODES + 255) / 256, 256>>>();
    k_convert  <<<N_EDGES / 256, 256>>>(ei);               // + degree histogram
    k_scan     <<<1, 1024>>>();                            // rowptr + cursor
    k_scatter  <<<N_EDGES / 256, 256>>>();                 // CSR col
    k_gemm0    <<<(N_NODES + 127) / 128, 256>>>(x, W0);
    k_nodeinit0<<<N_NODES / 8, 256>>>(a_src0, a_dst0);
    k_pull0    <<<N_NODES / 8, 256>>>(b0);                 // agg + softmax + relu fused
    k_gemm1    <<<(N_NODES + 127) / 128, 256>>>(W1);
    k_nodeinit1<<<N_NODES / 8, 256>>>(a_src1, a_dst1);
    k_pull1    <<<N_NODES / 8, 256>>>(b1, out);            // agg + softmax + bias fused
}

// round 15
// speedup vs baseline: 1.0107x; 1.0107x over previous
#include <cuda_runtime.h>
#include <cstdint>

#define N_NODES 50000
#define N_EDGES 1600000
#define IN_DIM  256
#define HID     128
#define NCLS    40
#define NEG     0.2f
#define FULL    0xffffffffu

// ---------------- scratch (device globals: allocation-free) ----------------
__device__ __align__(16) float g_h0[(size_t)N_NODES * HID];   // layer0 transformed feats
__device__ __align__(16) float g_hr[(size_t)N_NODES * HID];   // relu(layer0 out)
__device__ __align__(16) float g_h1[(size_t)N_NODES * NCLS];
__device__ float g_as0[N_NODES], g_ad0[N_NODES];
__device__ float g_as1[N_NODES], g_ad1[N_NODES];
__device__ int   g_src[N_EDGES], g_dst[N_EDGES];
__device__ int   g_col[N_EDGES];                  // CSR: src ids grouped by dst
__device__ int   g_deg[N_NODES];
__device__ int   g_rowptr[N_NODES + 1];
__device__ int   g_cur[N_NODES];

__device__ __forceinline__ float lrelu(float v) { return v > 0.f ? v : NEG * v; }
__device__ __forceinline__ int clampN(int v) {
    v = v < 0 ? 0 : v;
    return v >= N_NODES ? N_NODES - 1 : v;
}

// ---------------- zero degree histogram ----------------
__global__ void k_zero() {
    int i = blockIdx.x * blockDim.x + threadIdx.x;
    if (i < N_NODES) g_deg[i] = 0;
}

// ------- edge index load (dtype-robust) + degree histogram fused -------
// JAX default config disables x64, so the "int64" edge_index is usually int32.
// If genuine little-endian int64, all high words are zero (ids < 50000).
__global__ void k_convert(const int* __restrict__ ei32) {
    int i = blockIdx.x * blockDim.x + threadIdx.x;
    if (i >= N_EDGES) return;
    bool is64 = (ei32[1] == 0) & (ei32[3] == 0) & (ei32[5] == 0) & (ei32[7] == 0)
              & (ei32[9] == 0) & (ei32[11] == 0) & (ei32[13] == 0) & (ei32[15] == 0);
    int s, t;
    if (is64) {
        const long long* e = reinterpret_cast<const long long*>(ei32);
        s = (int)e[i];
        t = (int)e[i + N_EDGES];
    } else {
        s = ei32[i];
        t = ei32[i + N_EDGES];
    }
    s = clampN(s); t = clampN(t);
    g_src[i] = s;
    g_dst[i] = t;
    atomicAdd(&g_deg[t], 1);
}

// ---------------- single-block exclusive scan of degrees ----------------
__global__ void k_scan() {
    __shared__ int warp_sums[32];
    __shared__ int s_run;
    int tid  = threadIdx.x;          // 1024 threads
    int lane = tid & 31, wid = tid >> 5;
    if (tid == 0) s_run = 0;
    __syncthreads();
    for (int base = 0; base < N_NODES; base += 1024) {
        int i = base + tid;
        int v = (i < N_NODES) ? g_deg[i] : 0;
        int x = v;
        #pragma unroll
        for (int o = 1; o < 32; o <<= 1) {
            int t = __shfl_up_sync(FULL, x, o);
            if (lane >= o) x += t;
        }
        if (lane == 31) warp_sums[wid] = x;
        __syncthreads();
        if (wid == 0) {
            int w = warp_sums[lane];
            int y = w;
            #pragma unroll
            for (int o = 1; o < 32; o <<= 1) {
                int t = __shfl_up_sync(FULL, y, o);
                if (lane >= o) y += t;
            }
            warp_sums[lane] = y - w;          // exclusive warp offsets
        }
        __syncthreads();
        int excl = s_run + warp_sums[wid] + x - v;
        if (i < N_NODES) { g_rowptr[i] = excl; g_cur[i] = excl; }
        __syncthreads();                       // all reads of s_run done
        if (tid == 1023) s_run += warp_sums[31] + x;
        __syncthreads();
    }
    if (tid == 0) g_rowptr[N_NODES] = s_run;
}

// ---------------- scatter edges into CSR buckets ----------------
__global__ void k_scatter() {
    int i = blockIdx.x * blockDim.x + threadIdx.x;   // exact grid
    int t = g_dst[i];
    int pos = atomicAdd(&g_cur[t], 1);
    g_col[pos] = g_src[i];
}

// ---------------- layer0 GEMM: h0 = x[50000,256] @ W0[128,256]^T ------------
__global__ __launch_bounds__(256) void k_gemm0(const float* __restrict__ A,
                                               const float* __restrict__ B) {
    __shared__ float As[16][132];
    __shared__ float Bs[16][132];
    int tid = threadIdx.x;
    int m0  = blockIdx.x * 128;
    int tx  = tid & 15;
    int ty  = tid >> 4;
    float acc[8][8] = {};

    for (int k0 = 0; k0 < IN_DIM; k0 += 16) {
        #pragma unroll
        for (int i = 0; i < 2; i++) {
            int li  = tid + i * 256;
            int row = li >> 2, f4 = li & 3;
            int gr  = m0 + row;
            float4 v = (gr < N_NODES)
                ? *reinterpret_cast<const float4*>(A + (size_t)gr * IN_DIM + k0 + f4 * 4)
                : make_float4(0.f, 0.f, 0.f, 0.f);
            As[f4*4+0][row] = v.x; As[f4*4+1][row] = v.y;
            As[f4*4+2][row] = v.z; As[f4*4+3][row] = v.w;

            float4 w = *reinterpret_cast<const float4*>(B + (size_t)row * IN_DIM + k0 + f4 * 4);
            Bs[f4*4+0][row] = w.x; Bs[f4*4+1][row] = w.y;
            Bs[f4*4+2][row] = w.z; Bs[f4*4+3][row] = w.w;
        }
        __syncthreads();
        #pragma unroll
        for (int k = 0; k < 16; k++) {
            float a[8], b[8];
            #pragma unroll
            for (int i = 0; i < 8; i++) a[i] = As[k][ty * 8 + i];
            #pragma unroll
            for (int j = 0; j < 8; j++) b[j] = Bs[k][tx * 8 + j];
            #pragma unroll
            for (int i = 0; i < 8; i++)
                #pragma unroll
                for (int j = 0; j < 8; j++) acc[i][j] += a[i] * b[j];
        }
        __syncthreads();
    }
    #pragma unroll
    for (int i = 0; i < 8; i++) {
        int r = m0 + ty * 8 + i;
        if (r < N_NODES) {
            float* cp = g_h0 + (size_t)r * HID + tx * 8;
            *reinterpret_cast<float4*>(cp)     = make_float4(acc[i][0], acc[i][1], acc[i][2], acc[i][3]);
            *reinterpret_cast<float4*>(cp + 4) = make_float4(acc[i][4], acc[i][5], acc[i][6], acc[i][7]);
        }
    }
}

// ---------------- layer0 node init: alpha dot products only ----------------
__global__ __launch_bounds__(256) void k_nodeinit0(const float* __restrict__ av,
                                                   const float* __restrict__ dv) {
    int n    = blockIdx.x * 8 + (threadIdx.x >> 5);
    int lane = threadIdx.x & 31;
    float4 h  = *reinterpret_cast<const float4*>(g_h0 + (size_t)n * HID + lane * 4);
    float4 a4 = *reinterpret_cast<const float4*>(av + lane * 4);
    float4 d4 = *reinterpret_cast<const float4*>(dv + lane * 4);
    float s = h.x*a4.x + h.y*a4.y + h.z*a4.z + h.w*a4.w;
    float d = h.x*d4.x + h.y*d4.y + h.z*d4.z + h.w*d4.w;
    #pragma unroll
    for (int o = 16; o; o >>= 1) {
        s += __shfl_xor_sync(FULL, s, o);
        d += __shfl_xor_sync(FULL, d, o);
    }
    if (lane == 0) { g_as0[n] = s; g_ad0[n] = d; }
}

// ------- layer0 pull aggregation + softmax + finalize (fused), warp/node -------
__global__ __launch_bounds__(256) void k_pull0(const float* __restrict__ b0) {
    int n    = blockIdx.x * 8 + (threadIdx.x >> 5);      // exact: 6250*8 = 50000
    int lane = threadIdx.x & 31;
    const float* hp = g_h0 + (size_t)n * HID + lane * 4;
    float4 hs  = *reinterpret_cast<const float4*>(hp);
    float adn  = g_ad0[n];
    float exs  = __expf(lrelu(g_as0[n] + adn));          // self-loop (no max-shift; safe range)
    float4 acc = make_float4(hs.x*exs, hs.y*exs, hs.z*exs, hs.w*exs);
    float den  = (lane == 0) ? exs : 0.f;

    int beg = g_rowptr[n], end = g_rowptr[n + 1];
    for (int base = beg; base < end; base += 32) {
        int e = base + lane;
        int s = 0; float ex = 0.f;
        if (e < end) {
            s  = g_col[e];
            ex = __expf(lrelu(g_as0[s] + adn));
            den += ex;
        }
        int cnt = end - base; if (cnt > 32) cnt = 32;
        if (cnt == 32) {
            #pragma unroll 8
            for (int j = 0; j < 32; j++) {
                float exj = __shfl_sync(FULL, ex, j);
                int   sj  = __shfl_sync(FULL, s, j);
                float4 h = *reinterpret_cast<const float4*>(g_h0 + (size_t)sj * HID + lane * 4);
                acc.x += h.x*exj; acc.y += h.y*exj; acc.z += h.z*exj; acc.w += h.w*exj;
            }
        } else {
            for (int j = 0; j < cnt; j++) {
                float exj = __shfl_sync(FULL, ex, j);
                int   sj  = __shfl_sync(FULL, s, j);
                float4 h = *reinterpret_cast<const float4*>(g_h0 + (size_t)sj * HID + lane * 4);
                acc.x += h.x*exj; acc.y += h.y*exj; acc.z += h.z*exj; acc.w += h.w*exj;
            }
        }
    }
    #pragma unroll
    for (int o = 16; o; o >>= 1) den += __shfl_xor_sync(FULL, den, o);
    float inv = __fdividef(1.f, den);
    float4 b = *reinterpret_cast<const float4*>(b0 + lane * 4);
    float4 r;
    r.x = fmaxf(acc.x*inv + b.x, 0.f);
    r.y = fmaxf(acc.y*inv + b.y, 0.f);
    r.z = fmaxf(acc.z*inv + b.z, 0.f);
    r.w = fmaxf(acc.w*inv + b.w, 0.f);
    *reinterpret_cast<float4*>(g_hr + (size_t)n * HID + lane * 4) = r;
}

// ---------------- layer1 GEMM: h1 = hr[50000,128] @ W1[40,128]^T -------------
__global__ __launch_bounds__(256) void k_gemm1(const float* __restrict__ B) {
    __shared__ float hs[32][132];
    __shared__ float ws[32][42];
    int tid = threadIdx.x;
    int m0  = blockIdx.x * 128;
    int tx  = tid & 7;
    int ty  = tid >> 3;
    float acc[4][5] = {};

    for (int k0 = 0; k0 < HID; k0 += 32) {
        #pragma unroll
        for (int i = 0; i < 4; i++) {
            int li  = tid + i * 256;
            int row = li >> 3, f4 = li & 7;
            int gr  = m0 + row;
            float4 v = (gr < N_NODES)
                ? *reinterpret_cast<const float4*>(g_hr + (size_t)gr * HID + k0 + f4 * 4)
                : make_float4(0.f, 0.f, 0.f, 0.f);
            hs[f4*4+0][row] = v.x; hs[f4*4+1][row] = v.y;
            hs[f4*4+2][row] = v.z; hs[f4*4+3][row] = v.w;
        }
        for (int idx = tid; idx < 40 * 32; idx += 256) {
            int j = idx >> 5, k = idx & 31;
            ws[k][j] = B[(size_t)j * HID + k0 + k];
        }
        __syncthreads();
        #pragma unroll
        for (int k = 0; k < 32; k++) {
            float a[4], b[5];
            #pragma unroll
            for (int i = 0; i < 4; i++) a[i] = hs[k][ty * 4 + i];
            #pragma unroll
            for (int j = 0; j < 5; j++) b[j] = ws[k][tx * 5 + j];
            #pragma unroll
            for (int i = 0; i < 4; i++)
                #pragma unroll
                for (int j = 0; j < 5; j++) acc[i][j] += a[i] * b[j];
        }
        __syncthreads();
    }
    #pragma unroll
    for (int i = 0; i < 4; i++) {
        int r = m0 + ty * 4 + i;
        if (r < N_NODES)
            #pragma unroll
            for (int j = 0; j < 5; j++)
                g_h1[(size_t)r * NCLS + tx * 5 + j] = acc[i][j];
    }
}

// ---------------- layer1 node init: alpha dots only ----------------
__global__ __launch_bounds__(256) void k_nodeinit1(const float* __restrict__ av,
                                                   const float* __restrict__ dv) {
    int n    = blockIdx.x * 8 + (threadIdx.x >> 5);
    int lane = threadIdx.x & 31;
    const float* hp = g_h1 + (size_t)n * NCLS;
    float ha = hp[lane];
    float hb = (lane < 8) ? hp[32 + lane] : 0.f;
    float s = ha * av[lane] + ((lane < 8) ? hb * av[32 + lane] : 0.f);
    float d = ha * dv[lane] + ((lane < 8) ? hb * dv[32 + lane] : 0.f);
    #pragma unroll
    for (int o = 16; o; o >>= 1) {
        s += __shfl_xor_sync(FULL, s, o);
        d += __shfl_xor_sync(FULL, d, o);
    }
    if (lane == 0) { g_as1[n] = s; g_ad1[n] = d; }
}

// ------- layer1 pull aggregation + finalize (fused), warp/node -------
__global__ __launch_bounds__(256) void k_pull1(const float* __restrict__ b1,
                                               float* __restrict__ out) {
    int n    = blockIdx.x * 8 + (threadIdx.x >> 5);
    int lane = threadIdx.x & 31;
    float adn = g_ad1[n];
    float exs = __expf(lrelu(g_as1[n] + adn));
    float4 acc = make_float4(0.f, 0.f, 0.f, 0.f);
    if (lane < 10) {
        float4 h = *reinterpret_cast<const float4*>(g_h1 + (size_t)n * NCLS + lane * 4);
        acc = make_float4(h.x*exs, h.y*exs, h.z*exs, h.w*exs);
    }
    float den = (lane == 0) ? exs : 0.f;

    int beg = g_rowptr[n], end = g_rowptr[n + 1];
    for (int base = beg; base < end; base += 32) {
        int e = base + lane;
        int s = 0; float ex = 0.f;
        if (e < end) {
            s  = g_col[e];
            ex = __expf(lrelu(g_as1[s] + adn));
            den += ex;
        }
        int cnt = end - base; if (cnt > 32) cnt = 32;
        #pragma unroll 8
        for (int j = 0; j < cnt; j++) {
            float exj = __shfl_sync(FULL, ex, j);
            int   sj  = __shfl_sync(FULL, s, j);
            if (lane < 10) {
                float4 h = *reinterpret_cast<const float4*>(g_h1 + (size_t)sj * NCLS + lane * 4);
                acc.x += h.x*exj; acc.y += h.y*exj; acc.z += h.z*exj; acc.w += h.w*exj;
            }
        }
    }
    #pragma unroll
    for (int o = 16; o; o >>= 1) den += __shfl_xor_sync(FULL, den, o);
    float inv = __fdividef(1.f, den);
    if (lane < 10) {
        const float* bp = b1 + lane * 4;
        float* op = out + (size_t)n * NCLS + lane * 4;
        op[0] = acc.x*inv + bp[0];
        op[1] = acc.y*inv + bp[1];
        op[2] = acc.z*inv + bp[2];
        op[3] = acc.w*inv + bp[3];
    }
}

// ---------------- launch ----------------
extern "C" void kernel_launch(void* const* d_in, const int* in_sizes, int n_in,
                              void* d_out, int out_size) {
    const float* x      = (const float*)d_in[0];
    const int*   ei     = (const int*)d_in[1];       // int32 or int64 — sniffed on device
    const float* W0     = (const float*)d_in[2];
    const float* a_src0 = (const float*)d_in[3];
    const float* a_dst0 = (const float*)d_in[4];
    const float* b0     = (const float*)d_in[5];
    const float* W1     = (const float*)d_in[6];
    const float* a_src1 = (const float*)d_in[7];
    const float* a_dst1 = (const float*)d_in[8];
    const float* b1     = (const float*)d_in[9];
    float*       out    = (float*)d_out;

    k_zero     <<<(N_NODES + 255) / 256, 256>>>();
    k_convert  <<<N_EDGES / 256, 256>>>(ei);               // + degree histogram
    k_scan     <<<1, 1024>>>();                            // rowptr + cursor
    k_scatter  <<<N_EDGES / 256, 256>>>();                 // CSR col
    k_gemm0    <<<(N_NODES + 127) / 128, 256>>>(x, W0);
    k_nodeinit0<<<N_NODES / 8, 256>>>(a_src0, a_dst0);
    k_pull0    <<<N_NODES / 8, 256>>>(b0);                 // agg + softmax + relu fused
    k_gemm1    <<<(N_NODES + 127) / 128, 256>>>(W1);
    k_nodeinit1<<<N_NODES / 8, 256>>>(a_src1, a_dst1);
    k_pull1    <<<N_NODES / 8, 256>>>(b1, out);            // agg + softmax + bias fused
}

// round 16
// speedup vs baseline: 1.0194x; 1.0086x over previous
#include <cuda_runtime.h>
#include <cstdint>

#define N_NODES 50000
#define N_EDGES 1600000
#define IN_DIM  256
#define HID     128
#define NCLS    40
#define NEG     0.2f
#define FULL    0xffffffffu

// ---------------- scratch (device globals: allocation-free) ----------------
__device__ __align__(16) float g_h0[(size_t)N_NODES * HID];   // layer0 transformed feats
__device__ __align__(16) float g_hr[(size_t)N_NODES * HID];   // relu(layer0 out)
__device__ __align__(16) float g_h1[(size_t)N_NODES * NCLS];
__device__ float g_as0[N_NODES], g_ad0[N_NODES];
__device__ float g_as1[N_NODES], g_ad1[N_NODES];
__device__ int   g_src[N_EDGES], g_dst[N_EDGES];
__device__ int   g_col[N_EDGES];                  // CSR: src ids grouped by dst
__device__ int   g_deg[N_NODES];
__device__ int   g_rowptr[N_NODES + 1];
__device__ int   g_cur[N_NODES];

__device__ __forceinline__ float lrelu(float v) { return v > 0.f ? v : NEG * v; }
__device__ __forceinline__ int clampN(int v) {
    v = v < 0 ? 0 : v;
    return v >= N_NODES ? N_NODES - 1 : v;
}

// ---------------- zero degree histogram ----------------
__global__ void k_zero() {
    int i = blockIdx.x * blockDim.x + threadIdx.x;
    if (i < N_NODES) g_deg[i] = 0;
}

// ------- edge index load (dtype-robust) + degree histogram fused -------
// JAX default config disables x64, so the "int64" edge_index is usually int32.
// If genuine little-endian int64, all high words are zero (ids < 50000).
__global__ void k_convert(const int* __restrict__ ei32) {
    int i = blockIdx.x * blockDim.x + threadIdx.x;
    if (i >= N_EDGES) return;
    bool is64 = (ei32[1] == 0) & (ei32[3] == 0) & (ei32[5] == 0) & (ei32[7] == 0)
              & (ei32[9] == 0) & (ei32[11] == 0) & (ei32[13] == 0) & (ei32[15] == 0);
    int s, t;
    if (is64) {
        const long long* e = reinterpret_cast<const long long*>(ei32);
        s = (int)e[i];
        t = (int)e[i + N_EDGES];
    } else {
        s = ei32[i];
        t = ei32[i + N_EDGES];
    }
    s = clampN(s); t = clampN(t);
    g_src[i] = s;
    g_dst[i] = t;
    atomicAdd(&g_deg[t], 1);
}

// ---------------- single-block exclusive scan of degrees ----------------
__global__ void k_scan() {
    __shared__ int warp_sums[32];
    __shared__ int s_run;
    int tid  = threadIdx.x;          // 1024 threads
    int lane = tid & 31, wid = tid >> 5;
    if (tid == 0) s_run = 0;
    __syncthreads();
    for (int base = 0; base < N_NODES; base += 1024) {
        int i = base + tid;
        int v = (i < N_NODES) ? g_deg[i] : 0;
        int x = v;
        #pragma unroll
        for (int o = 1; o < 32; o <<= 1) {
            int t = __shfl_up_sync(FULL, x, o);
            if (lane >= o) x += t;
        }
        if (lane == 31) warp_sums[wid] = x;
        __syncthreads();
        if (wid == 0) {
            int w = warp_sums[lane];
            int y = w;
            #pragma unroll
            for (int o = 1; o < 32; o <<= 1) {
                int t = __shfl_up_sync(FULL, y, o);
                if (lane >= o) y += t;
            }
            warp_sums[lane] = y - w;          // exclusive warp offsets
        }
        __syncthreads();
        int excl = s_run + warp_sums[wid] + x - v;
        if (i < N_NODES) { g_rowptr[i] = excl; g_cur[i] = excl; }
        __syncthreads();                       // all reads of s_run done
        if (tid == 1023) s_run += warp_sums[31] + x;
        __syncthreads();
    }
    if (tid == 0) g_rowptr[N_NODES] = s_run;
}

// ---------------- scatter edges into CSR buckets ----------------
__global__ void k_scatter() {
    int i = blockIdx.x * blockDim.x + threadIdx.x;   // exact grid
    int t = g_dst[i];
    int pos = atomicAdd(&g_cur[t], 1);
    g_col[pos] = g_src[i];
}

// ---------------- layer0 GEMM: h0 = x[50000,256] @ W0[128,256]^T ------------
__global__ __launch_bounds__(256) void k_gemm0(const float* __restrict__ A,
                                               const float* __restrict__ B) {
    __shared__ float As[16][132];
    __shared__ float Bs[16][132];
    int tid = threadIdx.x;
    int m0  = blockIdx.x * 128;
    int tx  = tid & 15;
    int ty  = tid >> 4;
    float acc[8][8] = {};

    for (int k0 = 0; k0 < IN_DIM; k0 += 16) {
        #pragma unroll
        for (int i = 0; i < 2; i++) {
            int li  = tid + i * 256;
            int row = li >> 2, f4 = li & 3;
            int gr  = m0 + row;
            float4 v = (gr < N_NODES)
                ? *reinterpret_cast<const float4*>(A + (size_t)gr * IN_DIM + k0 + f4 * 4)
                : make_float4(0.f, 0.f, 0.f, 0.f);
            As[f4*4+0][row] = v.x; As[f4*4+1][row] = v.y;
            As[f4*4+2][row] = v.z; As[f4*4+3][row] = v.w;

            float4 w = *reinterpret_cast<const float4*>(B + (size_t)row * IN_DIM + k0 + f4 * 4);
            Bs[f4*4+0][row] = w.x; Bs[f4*4+1][row] = w.y;
            Bs[f4*4+2][row] = w.z; Bs[f4*4+3][row] = w.w;
        }
        __syncthreads();
        #pragma unroll
        for (int k = 0; k < 16; k++) {
            float a[8], b[8];
            #pragma unroll
            for (int i = 0; i < 8; i++) a[i] = As[k][ty * 8 + i];
            #pragma unroll
            for (int j = 0; j < 8; j++) b[j] = Bs[k][tx * 8 + j];
            #pragma unroll
            for (int i = 0; i < 8; i++)
                #pragma unroll
                for (int j = 0; j < 8; j++) acc[i][j] += a[i] * b[j];
        }
        __syncthreads();
    }
    #pragma unroll
    for (int i = 0; i < 8; i++) {
        int r = m0 + ty * 8 + i;
        if (r < N_NODES) {
            float* cp = g_h0 + (size_t)r * HID + tx * 8;
            *reinterpret_cast<float4*>(cp)     = make_float4(acc[i][0], acc[i][1], acc[i][2], acc[i][3]);
            *reinterpret_cast<float4*>(cp + 4) = make_float4(acc[i][4], acc[i][5], acc[i][6], acc[i][7]);
        }
    }
}

// ---------------- layer0 node init: alpha dot products only ----------------
__global__ __launch_bounds__(256) void k_nodeinit0(const float* __restrict__ av,
                                                   const float* __restrict__ dv) {
    int n    = blockIdx.x * 8 + (threadIdx.x >> 5);
    int lane = threadIdx.x & 31;
    float4 h  = *reinterpret_cast<const float4*>(g_h0 + (size_t)n * HID + lane * 4);
    float4 a4 = *reinterpret_cast<const float4*>(av + lane * 4);
    float4 d4 = *reinterpret_cast<const float4*>(dv + lane * 4);
    float s = h.x*a4.x + h.y*a4.y + h.z*a4.z + h.w*a4.w;
    float d = h.x*d4.x + h.y*d4.y + h.z*d4.z + h.w*d4.w;
    #pragma unroll
    for (int o = 16; o; o >>= 1) {
        s += __shfl_xor_sync(FULL, s, o);
        d += __shfl_xor_sync(FULL, d, o);
    }
    if (lane == 0) { g_as0[n] = s; g_ad0[n] = d; }
}

// ------- layer0 pull aggregation + softmax + finalize (fused), warp/node -------
__global__ __launch_bounds__(256) void k_pull0(const float* __restrict__ b0) {
    int n    = blockIdx.x * 8 + (threadIdx.x >> 5);      // exact: 6250*8 = 50000
    int lane = threadIdx.x & 31;
    const float* hp = g_h0 + (size_t)n * HID + lane * 4;
    float4 hs  = *reinterpret_cast<const float4*>(hp);
    float adn  = g_ad0[n];
    float exs  = __expf(lrelu(g_as0[n] + adn));          // self-loop (no max-shift; safe range)
    float4 acc = make_float4(hs.x*exs, hs.y*exs, hs.z*exs, hs.w*exs);
    float den  = (lane == 0) ? exs : 0.f;

    int beg = g_rowptr[n], end = g_rowptr[n + 1];
    for (int base = beg; base < end; base += 32) {
        int e = base + lane;
        int s = 0; float ex = 0.f;
        if (e < end) {
            s  = g_col[e];
            ex = __expf(lrelu(g_as0[s] + adn));
            den += ex;
        }
        int cnt = end - base; if (cnt > 32) cnt = 32;
        if (cnt == 32) {
            #pragma unroll 8
            for (int j = 0; j < 32; j++) {
                float exj = __shfl_sync(FULL, ex, j);
                int   sj  = __shfl_sync(FULL, s, j);
                float4 h = *reinterpret_cast<const float4*>(g_h0 + (size_t)sj * HID + lane * 4);
                acc.x += h.x*exj; acc.y += h.y*exj; acc.z += h.z*exj; acc.w += h.w*exj;
            }
        } else {
            for (int j = 0; j < cnt; j++) {
                float exj = __shfl_sync(FULL, ex, j);
                int   sj  = __shfl_sync(FULL, s, j);
                float4 h = *reinterpret_cast<const float4*>(g_h0 + (size_t)sj * HID + lane * 4);
                acc.x += h.x*exj; acc.y += h.y*exj; acc.z += h.z*exj; acc.w += h.w*exj;
            }
        }
    }
    #pragma unroll
    for (int o = 16; o; o >>= 1) den += __shfl_xor_sync(FULL, den, o);
    float inv = __fdividef(1.f, den);
    float4 b = *reinterpret_cast<const float4*>(b0 + lane * 4);
    float4 r;
    r.x = fmaxf(acc.x*inv + b.x, 0.f);
    r.y = fmaxf(acc.y*inv + b.y, 0.f);
    r.z = fmaxf(acc.z*inv + b.z, 0.f);
    r.w = fmaxf(acc.w*inv + b.w, 0.f);
    *reinterpret_cast<float4*>(g_hr + (size_t)n * HID + lane * 4) = r;
}

// ---------------- layer1 GEMM: h1 = hr[50000,128] @ W1[40,128]^T -------------
__global__ __launch_bounds__(256) void k_gemm1(const float* __restrict__ B) {
    __shared__ float hs[32][132];
    __shared__ float ws[32][42];
    int tid = threadIdx.x;
    int m0  = blockIdx.x * 128;
    int tx  = tid & 7;
    int ty  = tid >> 3;
    float acc[4][5] = {};

    for (int k0 = 0; k0 < HID; k0 += 32) {
        #pragma unroll
        for (int i = 0; i < 4; i++) {
            int li  = tid + i * 256;
            int row = li >> 3, f4 = li & 7;
            int gr  = m0 + row;
            float4 v = (gr < N_NODES)
                ? *reinterpret_cast<const float4*>(g_hr + (size_t)gr * HID + k0 + f4 * 4)
                : make_float4(0.f, 0.f, 0.f, 0.f);
            hs[f4*4+0][row] = v.x; hs[f4*4+1][row] = v.y;
            hs[f4*4+2][row] = v.z; hs[f4*4+3][row] = v.w;
        }
        for (int idx = tid; idx < 40 * 32; idx += 256) {
            int j = idx >> 5, k = idx & 31;
            ws[k][j] = B[(size_t)j * HID + k0 + k];
        }
        __syncthreads();
        #pragma unroll
        for (int k = 0; k < 32; k++) {
            float a[4], b[5];
            #pragma unroll
            for (int i = 0; i < 4; i++) a[i] = hs[k][ty * 4 + i];
            #pragma unroll
            for (int j = 0; j < 5; j++) b[j] = ws[k][tx * 5 + j];
            #pragma unroll
            for (int i = 0; i < 4; i++)
                #pragma unroll
                for (int j = 0; j < 5; j++) acc[i][j] += a[i] * b[j];
        }
        __syncthreads();
    }
    #pragma unroll
    for (int i = 0; i < 4; i++) {
        int r = m0 + ty * 4 + i;
        if (r < N_NODES)
            #pragma unroll
            for (int j = 0; j < 5; j++)
                g_h1[(size_t)r * NCLS + tx * 5 + j] = acc[i][j];
    }
}

// ---------------- layer1 node init: alpha dots only ----------------
__global__ __launch_bounds__(256) void k_nodeinit1(const float* __restrict__ av,
                                                   const float* __restrict__ dv) {
    int n    = blockIdx.x * 8 + (threadIdx.x >> 5);
    int lane = threadIdx.x & 31;
    const float* hp = g_h1 + (size_t)n * NCLS;
    float ha = hp[lane];
    float hb = (lane < 8) ? hp[32 + lane] : 0.f;
    float s = ha * av[lane] + ((lane < 8) ? hb * av[32 + lane] : 0.f);
    float d = ha * dv[lane] + ((lane < 8) ? hb * dv[32 + lane] : 0.f);
    #pragma unroll
    for (int o = 16; o; o >>= 1) {
        s += __shfl_xor_sync(FULL, s, o);
        d += __shfl_xor_sync(FULL, d, o);
    }
    if (lane == 0) { g_as1[n] = s; g_ad1[n] = d; }
}

// ------- layer1 pull aggregation + finalize (fused), warp/node -------
__global__ __launch_bounds__(256) void k_pull1(const float* __restrict__ b1,
                                               float* __restrict__ out) {
    int n    = blockIdx.x * 8 + (threadIdx.x >> 5);
    int lane = threadIdx.x & 31;
    float adn = g_ad1[n];
    float exs = __expf(lrelu(g_as1[n] + adn));
    float4 acc = make_float4(0.f, 0.f, 0.f, 0.f);
    if (lane < 10) {
        float4 h = *reinterpret_cast<const float4*>(g_h1 + (size_t)n * NCLS + lane * 4);
        acc = make_float4(h.x*exs, h.y*exs, h.z*exs, h.w*exs);
    }
    float den = (lane == 0) ? exs : 0.f;

    int beg = g_rowptr[n], end = g_rowptr[n + 1];
    for (int base = beg; base < end; base += 32) {
        int e = base + lane;
        int s = 0; float ex = 0.f;
        if (e < end) {
            s  = g_col[e];
            ex = __expf(lrelu(g_as1[s] + adn));
            den += ex;
        }
        int cnt = end - base; if (cnt > 32) cnt = 32;
        #pragma unroll 8
        for (int j = 0; j < cnt; j++) {
            float exj = __shfl_sync(FULL, ex, j);
            int   sj  = __shfl_sync(FULL, s, j);
            if (lane < 10) {
                float4 h = *reinterpret_cast<const float4*>(g_h1 + (size_t)sj * NCLS + lane * 4);
                acc.x += h.x*exj; acc.y += h.y*exj; acc.z += h.z*exj; acc.w += h.w*exj;
            }
        }
    }
    #pragma unroll
    for (int o = 16; o; o >>= 1) den += __shfl_xor_sync(FULL, den, o);
    float inv = __fdividef(1.f, den);
    if (lane < 10) {
        const float* bp = b1 + lane * 4;
        float* op = out + (size_t)n * NCLS + lane * 4;
        op[0] = acc.x*inv + bp[0];
        op[1] = acc.y*inv + bp[1];
        op[2] = acc.z*inv + bp[2];
        op[3] = acc.w*inv + bp[3];
    }
}

// ---------------- launch ----------------
extern "C" void kernel_launch(void* const* d_in, const int* in_sizes, int n_in,
                              void* d_out, int out_size) {
    const float* x      = (const float*)d_in[0];
    const int*   ei     = (const int*)d_in[1];       // int32 or int64 — sniffed on device
    const float* W0     = (const float*)d_in[2];
    const float* a_src0 = (const float*)d_in[3];
    const float* a_dst0 = (const float*)d_in[4];
    const float* b0     = (const float*)d_in[5];
    const float* W1     = (const float*)d_in[6];
    const float* a_src1 = (const float*)d_in[7];
    const float* a_dst1 = (const float*)d_in[8];
    const float* b1     = (const float*)d_in[9];
    float*       out    = (float*)d_out;

    k_zero     <<<(N_NODES + 255) / 256, 256>>>();
    k_convert  <<<N_EDGES / 256, 256>>>(ei);               // + degree histogram
    k_scan     <<<1, 1024>>>();                            // rowptr + cursor
    k_scatter  <<<N_EDGES / 256, 256>>>();                 // CSR col
    k_gemm0    <<<(N_NODES + 127) / 128, 256>>>(x, W0);
    k_nodeinit0<<<N_NODES / 8, 256>>>(a_src0, a_dst0);
    k_pull0    <<<N_NODES / 8, 256>>>(b0);                 // agg + softmax + relu fused
    k_gemm1    <<<(N_NODES + 127) / 128, 256>>>(W1);
    k_nodeinit1<<<N_NODES / 8, 256>>>(a_src1, a_dst1);
    k_pull1    <<<N_NODES / 8, 256>>>(b1, out);            // agg + softmax + bias fused
}